// round 1
// baseline (speedup 1.0000x reference)
#include <cuda_runtime.h>
#include <cuda_bf16.h>

// Batched 1D linear interpolation with clamped extrapolation.
// t: [B, N] sorted per row, v: [B, N], r: [B, M]  ->  out: [B, M]
// One CTA per row. t staged into skewed SMEM (binary search probes at
// power-of-2 strides would otherwise all land in bank 0), v staged plain.
// Each thread owns 16 consecutive queries, processed as 4 batches of 4
// register-interleaved binary searches for LDS latency hiding.

#define NN 4096
#define MM 4096
#define THREADS 256
#define QPT (MM / THREADS)          // 16 queries per thread
#define SKEW(i) ((i) + ((i) >> 5))  // bank-conflict skew for power-of-2 probes

__global__ __launch_bounds__(THREADS, 1)
void interp1d_kernel(const float* __restrict__ t,
                     const float* __restrict__ v,
                     const float* __restrict__ r,
                     float* __restrict__ out) {
    __shared__ float ts[NN + (NN >> 5)];  // skewed: 4224 floats
    __shared__ float vs[NN];

    const int row = blockIdx.x;
    const float* trow = t + (size_t)row * NN;
    const float* vrow = v + (size_t)row * NN;
    const float* rrow = r + (size_t)row * MM;
    float*       orow = out + (size_t)row * MM;
    const int tid = threadIdx.x;

    // ---- Stage knots into SMEM (coalesced float4 loads) ----
    const float4* t4 = reinterpret_cast<const float4*>(trow);
    const float4* v4 = reinterpret_cast<const float4*>(vrow);
    #pragma unroll
    for (int i = 0; i < NN / 4 / THREADS; i++) {   // 4 iterations
        int i4 = tid + i * THREADS;
        float4 tv = t4[i4];
        float4 vv = v4[i4];
        int b = i4 * 4;
        ts[SKEW(b + 0)] = tv.x;
        ts[SKEW(b + 1)] = tv.y;
        ts[SKEW(b + 2)] = tv.z;
        ts[SKEW(b + 3)] = tv.w;
        vs[b + 0] = vv.x;
        vs[b + 1] = vv.y;
        vs[b + 2] = vv.z;
        vs[b + 3] = vv.w;
    }
    __syncthreads();

    const float tfirst = ts[SKEW(0)];
    const float tlast  = ts[SKEW(NN - 1)];
    const float vfirst = vs[0];
    const float vlast  = vs[NN - 1];

    const int qbase = tid * QPT;

    #pragma unroll
    for (int b = 0; b < QPT / 4; b++) {
        // coalesced-in-aggregate float4 query load
        float4 rq = *reinterpret_cast<const float4*>(rrow + qbase + b * 4);
        float rv[4] = {rq.x, rq.y, rq.z, rq.w};

        // pos[q] = count of t <= r  (searchsorted side='right'), in [0, NN]
        int pos[4] = {0, 0, 0, 0};
        #pragma unroll
        for (int step = NN / 2; step >= 1; step >>= 1) {
            #pragma unroll
            for (int q = 0; q < 4; q++) {
                int np = pos[q] + step;
                float val = ts[SKEW(np - 1)];
                pos[q] = (val <= rv[q]) ? np : pos[q];
            }
        }

        float res[4];
        #pragma unroll
        for (int q = 0; q < 4; q++) {
            int idx = pos[q];
            idx = (idx < 1) ? 1 : idx;
            idx = (idx > NN - 1) ? NN - 1 : idx;
            float t0 = ts[SKEW(idx - 1)];
            float t1 = ts[SKEW(idx)];
            float v0 = vs[idx - 1];
            float v1 = vs[idx];
            float d = t1 - t0;
            float denom = (d == 0.0f) ? 1.0f : d;
            float o = v0 + (rv[q] - t0) / denom * (v1 - v0);
            // clamped extrapolation, matching the reference exactly
            o = (rv[q] < tfirst) ? vfirst : o;
            o = (rv[q] > tlast)  ? vlast  : o;
            res[q] = o;
        }

        float4 oq = make_float4(res[0], res[1], res[2], res[3]);
        *reinterpret_cast<float4*>(orow + qbase + b * 4) = oq;
    }
}

extern "C" void kernel_launch(void* const* d_in, const int* in_sizes, int n_in,
                              void* d_out, int out_size) {
    const float* t = (const float*)d_in[0];
    const float* v = (const float*)d_in[1];
    const float* r = (const float*)d_in[2];
    float* out = (float*)d_out;

    int B = in_sizes[0] / NN;  // 2048 for the reference shape
    interp1d_kernel<<<B, THREADS>>>(t, v, r, out);
}

// round 2
// speedup vs baseline: 1.0667x; 1.0667x over previous
#include <cuda_runtime.h>
#include <cuda_bf16.h>

// Batched 1D linear interpolation with clamped extrapolation.
// t: [B, N] sorted per row, v: [B, N], r: [B, M]  ->  out: [B, M]
//
// One CTA per row. Knots staged as interleaved (t,v) float2 pairs in SMEM.
// A per-row bucket table P[k] (ushort) gives, for each of KB uniform buckets
// over [tmin, tmax], the searchsorted position of the bucket's left boundary.
// A query in bucket k then only needs a tiny binary search in [P[k], P[k+1]]
// (expected width ~0.5 knots for uniform data; correct for any sorted t via
// a warp-vote refinement loop).

#define NN 4096
#define MM 4096
#define KB 8064                      // buckets (ushort table fits under 48KB smem)
#define THREADS 256
#define QPT (MM / THREADS)           // 16 queries per thread

__device__ __forceinline__ int bucket_of(float x, float tmin, float scale) {
    // monotone nondecreasing in x (IEEE sub/mul by positive const, trunc, clamp)
    int k = (int)((x - tmin) * scale);
    k = (k < 0) ? 0 : k;
    k = (k > KB - 1) ? KB - 1 : k;
    return k;
}

__global__ __launch_bounds__(THREADS, 1)
void interp1d_kernel(const float* __restrict__ t,
                     const float* __restrict__ v,
                     const float* __restrict__ r,
                     float* __restrict__ out) {
    __shared__ float2         tv[NN];   // 32768 B : (t[i], v[i]) pairs
    __shared__ unsigned short P[KB];    // 16128 B : P[KB] == NN handled inline

    const int row = blockIdx.x;
    const float* trow = t + (size_t)row * NN;
    const float* vrow = v + (size_t)row * NN;
    const float* rrow = r + (size_t)row * MM;
    float*       orow = out + (size_t)row * MM;
    const int tid = threadIdx.x;

    // ---- Stage knot pairs (stride-THREADS: coalesced LDG, conflict-free STS.64)
    #pragma unroll
    for (int i = 0; i < NN / THREADS; i++) {
        int j = tid + i * THREADS;
        tv[j] = make_float2(trow[j], vrow[j]);
    }
    // ---- Init bucket table to NN (buckets beyond the last knot)
    #pragma unroll
    for (int i = 0; i < (KB + THREADS - 1) / THREADS; i++) {
        int j = tid + i * THREADS;
        if (j < KB) P[j] = (unsigned short)NN;
    }
    __syncthreads();

    const float tmin   = tv[0].x;
    const float tmax   = tv[NN - 1].x;
    const float vfirst = tv[0].y;
    const float vlast  = tv[NN - 1].y;
    const float span   = tmax - tmin;
    const float scale  = (span > 0.0f) ? (float)KB / span : 0.0f;

    // ---- Build: bucket indices of sorted knots are sorted, so knot j owns
    //      table range (bucket(t[j-1]), bucket(t[j])] — disjoint scatter.
    #pragma unroll
    for (int i = 0; i < NN / THREADS; i++) {
        int j = tid + i * THREADS;
        int bj = bucket_of(tv[j].x, tmin, scale);
        int bp = (j == 0) ? -1 : bucket_of(tv[j - 1].x, tmin, scale);
        for (int k = bp + 1; k <= bj; k++) P[k] = (unsigned short)j;
    }
    __syncthreads();

    // ---- Queries: 16 per thread, 4 register-interleaved at a time
    #pragma unroll
    for (int b = 0; b < QPT / 4; b++) {
        float rv[4];
        #pragma unroll
        for (int q = 0; q < 4; q++)
            rv[q] = rrow[tid + (b * 4 + q) * THREADS];   // coalesced

        int lo[4], hi[4];
        #pragma unroll
        for (int q = 0; q < 4; q++) {
            int k = bucket_of(rv[q], tmin, scale);
            lo[q] = P[k];
            hi[q] = (k == KB - 1) ? NN : (int)P[k + 1];
        }

        // tiny refinement: pos = count(t <= r) within [lo, hi]
        // warp-uniform loop (vote) -> no divergence churn; expected 1-2 trips
        while (__any_sync(0xffffffffu,
                          (lo[0] < hi[0]) | (lo[1] < hi[1]) |
                          (lo[2] < hi[2]) | (lo[3] < hi[3]))) {
            #pragma unroll
            for (int q = 0; q < 4; q++) {
                if (lo[q] < hi[q]) {
                    int mid = (lo[q] + hi[q]) >> 1;
                    float tm = tv[mid].x;
                    if (tm <= rv[q]) lo[q] = mid + 1; else hi[q] = mid;
                }
            }
        }

        float res[4];
        #pragma unroll
        for (int q = 0; q < 4; q++) {
            int idx = lo[q];
            idx = (idx < 1) ? 1 : idx;
            idx = (idx > NN - 1) ? NN - 1 : idx;
            float2 p0 = tv[idx - 1];
            float2 p1 = tv[idx];
            float d = p1.x - p0.x;
            float denom = (d == 0.0f) ? 1.0f : d;
            float o = p0.y + (rv[q] - p0.x) / denom * (p1.y - p0.y);
            o = (rv[q] < tmin) ? vfirst : o;   // clamped extrapolation
            o = (rv[q] > tmax) ? vlast  : o;
            res[q] = o;
        }

        #pragma unroll
        for (int q = 0; q < 4; q++)
            orow[tid + (b * 4 + q) * THREADS] = res[q];
    }
}

extern "C" void kernel_launch(void* const* d_in, const int* in_sizes, int n_in,
                              void* d_out, int out_size) {
    const float* t = (const float*)d_in[0];
    const float* v = (const float*)d_in[1];
    const float* r = (const float*)d_in[2];
    float* out = (float*)d_out;

    int B = in_sizes[0] / NN;   // 2048 for the reference shape
    interp1d_kernel<<<B, THREADS>>>(t, v, r, out);
}